// round 3
// baseline (speedup 1.0000x reference)
#include <cuda_runtime.h>

#define B_  2
#define S_  2048
#define D_  1024
#define H_  16
#define HD_ 64
#define M_  (B_*S_)   // 4096

// Scratch (allocation-free rule: __device__ globals)
__device__ float g_q[B_*H_*S_*HD_];   // [b,h,s,d] 16MB
__device__ float g_k[B_*H_*S_*HD_];
__device__ float g_v[B_*H_*S_*HD_];
__device__ float g_att[B_*S_*D_];     // [b,s,h*64+d] 16MB

// ---------------------------------------------------------------------------
// 128x128x8 SIMT SGEMM, 256 threads, 8x8 per-thread microtile.
// C[M,1024] = A[M,1024] @ W[1024,1024] + bias
// qkv mode: scatter into [b,h,s,d] layout
// ---------------------------------------------------------------------------
__device__ __forceinline__ void sgemm_body(
    const float* __restrict__ A, const float* __restrict__ W,
    const float* __restrict__ bias, float* __restrict__ C, int qkv_layout)
{
    __shared__ float As[8][132];   // k-major, padded: conflict-free transpose store
    __shared__ float Bs[8][128];

    const int tid = threadIdx.x;
    const int tx = tid & 15, ty = tid >> 4;
    const int m0 = blockIdx.y * 128, n0 = blockIdx.x * 128;

    const int arow = tid >> 1;           // 0..127
    const int acol = (tid & 1) * 4;      // 0 or 4
    const int brow = tid >> 5;           // 0..7
    const int bcol = (tid & 31) * 4;     // 0..124

    const float* Aptr = A + (m0 + arow) * D_ + acol;
    const float* Wptr = W + brow * D_ + n0 + bcol;

    float acc[8][8];
    #pragma unroll
    for (int i = 0; i < 8; i++)
        #pragma unroll
        for (int j = 0; j < 8; j++) acc[i][j] = 0.f;

    for (int kt = 0; kt < D_ / 8; ++kt) {
        float4 a = *reinterpret_cast<const float4*>(Aptr + kt * 8);
        float4 b = *reinterpret_cast<const float4*>(Wptr + (size_t)kt * 8 * D_);
        As[acol + 0][arow] = a.x;
        As[acol + 1][arow] = a.y;
        As[acol + 2][arow] = a.z;
        As[acol + 3][arow] = a.w;
        *reinterpret_cast<float4*>(&Bs[brow][bcol]) = b;
        __syncthreads();
        #pragma unroll
        for (int kk = 0; kk < 8; kk++) {
            float4 a0 = *reinterpret_cast<const float4*>(&As[kk][ty * 4]);
            float4 a1 = *reinterpret_cast<const float4*>(&As[kk][ty * 4 + 64]);
            float4 b0 = *reinterpret_cast<const float4*>(&Bs[kk][tx * 4]);
            float4 b1 = *reinterpret_cast<const float4*>(&Bs[kk][tx * 4 + 64]);
            float av[8] = {a0.x, a0.y, a0.z, a0.w, a1.x, a1.y, a1.z, a1.w};
            float bv[8] = {b0.x, b0.y, b0.z, b0.w, b1.x, b1.y, b1.z, b1.w};
            #pragma unroll
            for (int i = 0; i < 8; i++)
                #pragma unroll
                for (int j = 0; j < 8; j++)
                    acc[i][j] += av[i] * bv[j];
        }
        __syncthreads();
    }

    #pragma unroll
    for (int i = 0; i < 8; i++) {
        int m = m0 + ty * 4 + (i & 3) + (i >> 2) * 64;
        #pragma unroll
        for (int j = 0; j < 8; j++) {
            int n = n0 + tx * 4 + (j & 3) + (j >> 2) * 64;
            float v = acc[i][j] + bias[n];
            if (qkv_layout) {
                int bb = m >> 11;          // m / S_
                int ss = m & (S_ - 1);
                int hh = n >> 6;
                int dd = n & 63;
                C[(((size_t)bb * H_ + hh) * S_ + ss) * HD_ + dd] = v;
            } else {
                C[(size_t)m * D_ + n] = v;
            }
        }
    }
}

__global__ __launch_bounds__(256)
void qkv_gemm_kernel(const float* __restrict__ x,
                     const float* __restrict__ Wq, const float* __restrict__ Wk,
                     const float* __restrict__ Wv,
                     const float* __restrict__ bq, const float* __restrict__ bk,
                     const float* __restrict__ bv)
{
    const float* W;
    const float* bias;
    float* out;
    if (blockIdx.z == 0)      { W = Wq; bias = bq; out = g_q; }
    else if (blockIdx.z == 1) { W = Wk; bias = bk; out = g_k; }
    else                      { W = Wv; bias = bv; out = g_v; }
    sgemm_body(x, W, bias, out, 1);
}

__global__ __launch_bounds__(256)
void out_gemm_kernel(const float* __restrict__ Wo, const float* __restrict__ bo,
                     float* __restrict__ out)
{
    sgemm_body(g_att, Wo, bo, out, 0);
}

// ---------------------------------------------------------------------------
// Flash attention: one block per (b, h, q-tile of 64 rows).
// 256 threads; thread t: row r = t>>2, quad qd = t&3.
//   scores: thread owns cols c = qd + 4j  (conflict-free K reads / P writes)
//   output: thread owns dims d = qd*16 + i (vectorizable V reads / O stores)
// ---------------------------------------------------------------------------
#define PADR 68
#define ATTN_SMEM (4 * 64 * PADR * sizeof(float))   // Q,K,V,P = 69632 B

__global__ __launch_bounds__(256)
void attn_kernel()
{
    extern __shared__ float sm[];
    float* Qs = sm;
    float* Ks = sm + 64 * PADR;
    float* Vs = sm + 2 * 64 * PADR;
    float* Ps = sm + 3 * 64 * PADR;

    const int t  = threadIdx.x;
    const int r  = t >> 2;     // 0..63
    const int qd = t & 3;
    const int qt = blockIdx.x;
    const int h  = blockIdx.y;
    const int b  = blockIdx.z;
    const float scale = 0.125f;   // 1/sqrt(64)

    const float* qp = g_q + (((size_t)b * H_ + h) * S_ + qt * 64) * HD_;
    const float* kp = g_k + ((size_t)b * H_ + h) * S_ * HD_;
    const float* vp = g_v + ((size_t)b * H_ + h) * S_ * HD_;

    // load Q tile [64,64]
    {
        int row = t >> 4;
        int c4  = (t & 15) * 4;
        #pragma unroll
        for (int i = 0; i < 4; i++) {
            int rr = row + i * 16;
            *reinterpret_cast<float4*>(&Qs[rr * PADR + c4]) =
                *reinterpret_cast<const float4*>(qp + rr * HD_ + c4);
        }
    }

    float m_i = -1e30f, l_i = 0.f;
    float o[16];
    #pragma unroll
    for (int i = 0; i < 16; i++) o[i] = 0.f;

    for (int kt = 0; kt < S_ / 64; ++kt) {
        __syncthreads();   // prior iteration done reading Ks/Vs/Ps
        {
            int row = t >> 4;
            int c4  = (t & 15) * 4;
            #pragma unroll
            for (int i = 0; i < 4; i++) {
                int rr = row + i * 16;
                *reinterpret_cast<float4*>(&Ks[rr * PADR + c4]) =
                    *reinterpret_cast<const float4*>(kp + (kt * 64 + rr) * HD_ + c4);
                *reinterpret_cast<float4*>(&Vs[rr * PADR + c4]) =
                    *reinterpret_cast<const float4*>(vp + (kt * 64 + rr) * HD_ + c4);
            }
        }
        __syncthreads();

        // scores s[j] = Q[r] . K[qd+4j]
        float s[16];
        #pragma unroll
        for (int j = 0; j < 16; j++) s[j] = 0.f;
        #pragma unroll
        for (int d4 = 0; d4 < 16; ++d4) {
            float4 qv = *reinterpret_cast<const float4*>(&Qs[r * PADR + d4 * 4]);
            #pragma unroll
            for (int j = 0; j < 16; j++) {
                float4 kv = *reinterpret_cast<const float4*>(&Ks[(qd + 4 * j) * PADR + d4 * 4]);
                s[j] += qv.x * kv.x + qv.y * kv.y + qv.z * kv.z + qv.w * kv.w;
            }
        }

        // scale + row max (4 lanes per row: shfl over lanes 1,2)
        #pragma unroll
        for (int j = 0; j < 16; j++) s[j] *= scale;
        float mx = s[0];
        #pragma unroll
        for (int j = 1; j < 16; j++) mx = fmaxf(mx, s[j]);
        mx = fmaxf(mx, __shfl_xor_sync(0xffffffffu, mx, 1));
        mx = fmaxf(mx, __shfl_xor_sync(0xffffffffu, mx, 2));

        float m_new = fmaxf(m_i, mx);
        float corr  = __expf(m_i - m_new);
        float ps = 0.f;
        #pragma unroll
        for (int j = 0; j < 16; j++) {
            float p = __expf(s[j] - m_new);
            ps += p;
            Ps[r * PADR + qd + 4 * j] = p;
        }
        ps += __shfl_xor_sync(0xffffffffu, ps, 1);
        ps += __shfl_xor_sync(0xffffffffu, ps, 2);
        l_i = l_i * corr + ps;
        m_i = m_new;
        #pragma unroll
        for (int i = 0; i < 16; i++) o[i] *= corr;
        __syncthreads();   // Ps visible to all

        // O[r][qd*16 + i] += sum_c P[r][c] * V[c][qd*16 + i]
        #pragma unroll
        for (int c = 0; c < 64; c++) {
            float pv = Ps[r * PADR + c];
            const float* vrow = &Vs[c * PADR + qd * 16];
            float4 v0 = *reinterpret_cast<const float4*>(vrow + 0);
            float4 v1 = *reinterpret_cast<const float4*>(vrow + 4);
            float4 v2 = *reinterpret_cast<const float4*>(vrow + 8);
            float4 v3 = *reinterpret_cast<const float4*>(vrow + 12);
            o[0]  += pv * v0.x; o[1]  += pv * v0.y; o[2]  += pv * v0.z; o[3]  += pv * v0.w;
            o[4]  += pv * v1.x; o[5]  += pv * v1.y; o[6]  += pv * v1.z; o[7]  += pv * v1.w;
            o[8]  += pv * v2.x; o[9]  += pv * v2.y; o[10] += pv * v2.z; o[11] += pv * v2.w;
            o[12] += pv * v3.x; o[13] += pv * v3.y; o[14] += pv * v3.z; o[15] += pv * v3.w;
        }
    }

    // epilogue: normalize, write attended[b, s, h*64 + d]
    float inv = 1.f / l_i;
    float* op = g_att + ((size_t)b * S_ + qt * 64 + r) * D_ + h * HD_ + qd * 16;
    #pragma unroll
    for (int i4 = 0; i4 < 4; i4++) {
        float4 v;
        v.x = o[i4 * 4 + 0] * inv;
        v.y = o[i4 * 4 + 1] * inv;
        v.z = o[i4 * 4 + 2] * inv;
        v.w = o[i4 * 4 + 3] * inv;
        *reinterpret_cast<float4*>(op + i4 * 4) = v;
    }
}

// ---------------------------------------------------------------------------
extern "C" void kernel_launch(void* const* d_in, const int* in_sizes, int n_in,
                              void* d_out, int out_size)
{
    const float* x  = (const float*)d_in[0];
    const float* Wq = (const float*)d_in[1];
    const float* bq = (const float*)d_in[2];
    const float* Wk = (const float*)d_in[3];
    const float* bk = (const float*)d_in[4];
    const float* Wv = (const float*)d_in[5];
    const float* bv = (const float*)d_in[6];
    const float* Wo = (const float*)d_in[7];
    const float* bo = (const float*)d_in[8];
    float* out = (float*)d_out;

    cudaFuncSetAttribute(attn_kernel,
                         cudaFuncAttributeMaxDynamicSharedMemorySize,
                         (int)ATTN_SMEM);

    dim3 gemm_grid(D_ / 128, M_ / 128, 3);          // (8, 32, 3)
    qkv_gemm_kernel<<<gemm_grid, 256>>>(x, Wq, Wk, Wv, bq, bk, bv);

    dim3 attn_grid(S_ / 64, H_, B_);                // (32, 16, 2)
    attn_kernel<<<attn_grid, 256, ATTN_SMEM>>>();

    dim3 out_grid(D_ / 128, M_ / 128, 1);           // (8, 32)
    out_gemm_kernel<<<out_grid, 256>>>(Wo, bo, out);
}

// round 4
// speedup vs baseline: 1.9955x; 1.9955x over previous
#include <cuda_runtime.h>

#define B_  2
#define S_  2048
#define D_  1024
#define H_  16
#define HD_ 64
#define M_  (B_*S_)   // 4096

// Scratch (allocation-free rule: __device__ globals)
__device__ float g_q[B_*H_*S_*HD_];   // [b,h,s,d] 16MB
__device__ float g_k[B_*H_*S_*HD_];
__device__ float g_v[B_*H_*S_*HD_];
__device__ float g_att[B_*S_*D_];     // [b,s,h*64+d] 16MB

// ---------------------------------------------------------------------------
// 128x128x8 SIMT SGEMM, 256 threads, 8x8 per-thread microtile. (unchanged)
// ---------------------------------------------------------------------------
__device__ __forceinline__ void sgemm_body(
    const float* __restrict__ A, const float* __restrict__ W,
    const float* __restrict__ bias, float* __restrict__ C, int qkv_layout)
{
    __shared__ float As[8][132];
    __shared__ float Bs[8][128];

    const int tid = threadIdx.x;
    const int tx = tid & 15, ty = tid >> 4;
    const int m0 = blockIdx.y * 128, n0 = blockIdx.x * 128;

    const int arow = tid >> 1;
    const int acol = (tid & 1) * 4;
    const int brow = tid >> 5;
    const int bcol = (tid & 31) * 4;

    const float* Aptr = A + (m0 + arow) * D_ + acol;
    const float* Wptr = W + brow * D_ + n0 + bcol;

    float acc[8][8];
    #pragma unroll
    for (int i = 0; i < 8; i++)
        #pragma unroll
        for (int j = 0; j < 8; j++) acc[i][j] = 0.f;

    for (int kt = 0; kt < D_ / 8; ++kt) {
        float4 a = *reinterpret_cast<const float4*>(Aptr + kt * 8);
        float4 b = *reinterpret_cast<const float4*>(Wptr + (size_t)kt * 8 * D_);
        As[acol + 0][arow] = a.x;
        As[acol + 1][arow] = a.y;
        As[acol + 2][arow] = a.z;
        As[acol + 3][arow] = a.w;
        *reinterpret_cast<float4*>(&Bs[brow][bcol]) = b;
        __syncthreads();
        #pragma unroll
        for (int kk = 0; kk < 8; kk++) {
            float4 a0 = *reinterpret_cast<const float4*>(&As[kk][ty * 4]);
            float4 a1 = *reinterpret_cast<const float4*>(&As[kk][ty * 4 + 64]);
            float4 b0 = *reinterpret_cast<const float4*>(&Bs[kk][tx * 4]);
            float4 b1 = *reinterpret_cast<const float4*>(&Bs[kk][tx * 4 + 64]);
            float av[8] = {a0.x, a0.y, a0.z, a0.w, a1.x, a1.y, a1.z, a1.w};
            float bv[8] = {b0.x, b0.y, b0.z, b0.w, b1.x, b1.y, b1.z, b1.w};
            #pragma unroll
            for (int i = 0; i < 8; i++)
                #pragma unroll
                for (int j = 0; j < 8; j++)
                    acc[i][j] += av[i] * bv[j];
        }
        __syncthreads();
    }

    #pragma unroll
    for (int i = 0; i < 8; i++) {
        int m = m0 + ty * 4 + (i & 3) + (i >> 2) * 64;
        #pragma unroll
        for (int j = 0; j < 8; j++) {
            int n = n0 + tx * 4 + (j & 3) + (j >> 2) * 64;
            float v = acc[i][j] + bias[n];
            if (qkv_layout) {
                int bb = m >> 11;
                int ss = m & (S_ - 1);
                int hh = n >> 6;
                int dd = n & 63;
                C[(((size_t)bb * H_ + hh) * S_ + ss) * HD_ + dd] = v;
            } else {
                C[(size_t)m * D_ + n] = v;
            }
        }
    }
}

__global__ __launch_bounds__(256)
void qkv_gemm_kernel(const float* __restrict__ x,
                     const float* __restrict__ Wq, const float* __restrict__ Wk,
                     const float* __restrict__ Wv,
                     const float* __restrict__ bq, const float* __restrict__ bk,
                     const float* __restrict__ bv)
{
    const float* W;
    const float* bias;
    float* out;
    if (blockIdx.z == 0)      { W = Wq; bias = bq; out = g_q; }
    else if (blockIdx.z == 1) { W = Wk; bias = bk; out = g_k; }
    else                      { W = Wv; bias = bv; out = g_v; }
    sgemm_body(x, W, bias, out, 1);
}

__global__ __launch_bounds__(256)
void out_gemm_kernel(const float* __restrict__ Wo, const float* __restrict__ bo,
                     float* __restrict__ out)
{
    sgemm_body(g_att, Wo, bo, out, 0);
}

// ---------------------------------------------------------------------------
// Flash attention v2: BQ=128 q-rows/block, BK=64 key chunks, 256 threads.
// Register-blocked 8x4 microtile GEMMs for both scores and PV.
//   thread (tx=tid&15, ty=tid>>4) owns rows r(i)=ty*4+(i&3)+(i>>2)*64 (8 rows)
//   scores phase: cols c = tx*4+j (j=0..3)
//   PV phase:     dims dv = tx*4+j ; P broadcast via shfl within 16-lane group
// smem: Qt[64][132] d-major (scale pre-applied), Kt[64][68] d-major, Vs[64][68]
// ---------------------------------------------------------------------------
#define BQ 128
#define BK 64
#define QP 132
#define KP 68
#define ATTN_SMEM ((64*QP + 64*KP + 64*KP) * sizeof(float))  // 68608 B

__global__ __launch_bounds__(256)
void attn_kernel()
{
    extern __shared__ float sm[];
    float* Qt = sm;                      // [d][r]  64 x 132
    float* Kt = sm + 64 * QP;            // [d][c]  64 x 68
    float* Vs = sm + 64 * QP + 64 * KP;  // [c][dv] 64 x 68

    const int tid  = threadIdx.x;
    const int tx   = tid & 15;
    const int ty   = tid >> 4;
    const int lane = tid & 31;
    const int qt = blockIdx.x, h = blockIdx.y, b = blockIdx.z;
    const float scale = 0.125f;   // 1/sqrt(64)

    const float* qp = g_q + (((size_t)b * H_ + h) * S_ + qt * BQ) * HD_;
    const float* kp = g_k + ((size_t)b * H_ + h) * S_ * HD_;
    const float* vp = g_v + ((size_t)b * H_ + h) * S_ * HD_;

    // Load Q tile [BQ x 64] -> Qt[d][r], scale folded in.
    // row = tid&127 (warp covers 32 distinct rows -> conflict-free stores)
    {
        int row = tid & 127;
        int cg  = tid >> 7;          // 0 or 1
        const float* src = qp + row * HD_ + cg * 32;
        #pragma unroll
        for (int ii = 0; ii < 8; ii++) {
            float4 v = *reinterpret_cast<const float4*>(src + ii * 4);
            int d = cg * 32 + ii * 4;
            Qt[(d + 0) * QP + row] = v.x * scale;
            Qt[(d + 1) * QP + row] = v.y * scale;
            Qt[(d + 2) * QP + row] = v.z * scale;
            Qt[(d + 3) * QP + row] = v.w * scale;
        }
    }

    float m_i[8], l_i[8], o[8][4];
    #pragma unroll
    for (int i = 0; i < 8; i++) {
        m_i[i] = -1e30f; l_i[i] = 0.f;
        o[i][0] = o[i][1] = o[i][2] = o[i][3] = 0.f;
    }

    for (int kt = 0; kt < S_ / BK; ++kt) {
        __syncthreads();   // prior iteration done reading Kt/Vs
        // Load K chunk -> Kt[d][c] (transposed, conflict-free: 32 distinct rows/warp)
        // and V chunk -> Vs[c][dv] (row-major)
        {
            int row = tid & 63;
            int cg  = tid >> 6;      // 0..3
            const float* ks = kp + (size_t)(kt * BK + row) * HD_ + cg * 16;
            const float* vsrc = vp + (size_t)(kt * BK + row) * HD_ + cg * 16;
            #pragma unroll
            for (int ii = 0; ii < 4; ii++) {
                float4 kv = *reinterpret_cast<const float4*>(ks + ii * 4);
                int d = cg * 16 + ii * 4;
                Kt[(d + 0) * KP + row] = kv.x;
                Kt[(d + 1) * KP + row] = kv.y;
                Kt[(d + 2) * KP + row] = kv.z;
                Kt[(d + 3) * KP + row] = kv.w;
                *reinterpret_cast<float4*>(&Vs[row * KP + cg * 16 + ii * 4]) =
                    *reinterpret_cast<const float4*>(vsrc + ii * 4);
            }
        }
        __syncthreads();

        // ---- scores: s[i][j] = sum_d Qt[d][r(i)] * Kt[d][tx*4+j]
        float s[8][4];
        #pragma unroll
        for (int i = 0; i < 8; i++)
            s[i][0] = s[i][1] = s[i][2] = s[i][3] = 0.f;

        #pragma unroll 8
        for (int d = 0; d < 64; d++) {
            float4 q0 = *reinterpret_cast<const float4*>(&Qt[d * QP + ty * 4]);
            float4 q1 = *reinterpret_cast<const float4*>(&Qt[d * QP + ty * 4 + 64]);
            float4 kv = *reinterpret_cast<const float4*>(&Kt[d * KP + tx * 4]);
            float qa[8] = {q0.x, q0.y, q0.z, q0.w, q1.x, q1.y, q1.z, q1.w};
            #pragma unroll
            for (int i = 0; i < 8; i++) {
                s[i][0] += qa[i] * kv.x;
                s[i][1] += qa[i] * kv.y;
                s[i][2] += qa[i] * kv.z;
                s[i][3] += qa[i] * kv.w;
            }
        }

        // ---- online softmax (row stats across 16-lane groups)
        #pragma unroll
        for (int i = 0; i < 8; i++) {
            float mx = fmaxf(fmaxf(s[i][0], s[i][1]), fmaxf(s[i][2], s[i][3]));
            mx = fmaxf(mx, __shfl_xor_sync(0xffffffffu, mx, 1));
            mx = fmaxf(mx, __shfl_xor_sync(0xffffffffu, mx, 2));
            mx = fmaxf(mx, __shfl_xor_sync(0xffffffffu, mx, 4));
            mx = fmaxf(mx, __shfl_xor_sync(0xffffffffu, mx, 8));
            float m_new = fmaxf(m_i[i], mx);
            float corr  = __expf(m_i[i] - m_new);
            float ps = 0.f;
            #pragma unroll
            for (int j = 0; j < 4; j++) {
                float p = __expf(s[i][j] - m_new);
                s[i][j] = p;
                ps += p;
            }
            ps += __shfl_xor_sync(0xffffffffu, ps, 1);
            ps += __shfl_xor_sync(0xffffffffu, ps, 2);
            ps += __shfl_xor_sync(0xffffffffu, ps, 4);
            ps += __shfl_xor_sync(0xffffffffu, ps, 8);
            l_i[i] = l_i[i] * corr + ps;
            m_i[i] = m_new;
            o[i][0] *= corr; o[i][1] *= corr; o[i][2] *= corr; o[i][3] *= corr;
        }

        // ---- PV: o[i][j] += sum_c P[r(i)][c] * Vs[c][tx*4+j]
        // P[r(i)][c] lives in register s[i][c&3] of lane ((lane&16)|(c>>2))
        #pragma unroll 4
        for (int c = 0; c < 64; c++) {
            int src = (lane & 16) | (c >> 2);
            float4 vv = *reinterpret_cast<const float4*>(&Vs[c * KP + tx * 4]);
            #pragma unroll
            for (int i = 0; i < 8; i++) {
                float pv = __shfl_sync(0xffffffffu, s[i][c & 3], src);
                o[i][0] += pv * vv.x;
                o[i][1] += pv * vv.y;
                o[i][2] += pv * vv.z;
                o[i][3] += pv * vv.w;
            }
        }
    }

    // epilogue: normalize, write attended[b, s, h*64 + dv]
    float* op = g_att + ((size_t)b * S_ + qt * BQ) * D_ + h * HD_;
    #pragma unroll
    for (int i = 0; i < 8; i++) {
        int r = ty * 4 + (i & 3) + (i >> 2) * 64;
        float inv = 1.f / l_i[i];
        float4 v;
        v.x = o[i][0] * inv;
        v.y = o[i][1] * inv;
        v.z = o[i][2] * inv;
        v.w = o[i][3] * inv;
        *reinterpret_cast<float4*>(op + (size_t)r * D_ + tx * 4) = v;
    }
}

// ---------------------------------------------------------------------------
extern "C" void kernel_launch(void* const* d_in, const int* in_sizes, int n_in,
                              void* d_out, int out_size)
{
    const float* x  = (const float*)d_in[0];
    const float* Wq = (const float*)d_in[1];
    const float* bq = (const float*)d_in[2];
    const float* Wk = (const float*)d_in[3];
    const float* bk = (const float*)d_in[4];
    const float* Wv = (const float*)d_in[5];
    const float* bv = (const float*)d_in[6];
    const float* Wo = (const float*)d_in[7];
    const float* bo = (const float*)d_in[8];
    float* out = (float*)d_out;

    cudaFuncSetAttribute(attn_kernel,
                         cudaFuncAttributeMaxDynamicSharedMemorySize,
                         (int)ATTN_SMEM);

    dim3 gemm_grid(D_ / 128, M_ / 128, 3);          // (8, 32, 3)
    qkv_gemm_kernel<<<gemm_grid, 256>>>(x, Wq, Wk, Wv, bq, bk, bv);

    dim3 attn_grid(S_ / BQ, H_, B_);                // (16, 16, 2)
    attn_kernel<<<attn_grid, 256, ATTN_SMEM>>>();

    dim3 out_grid(D_ / 128, M_ / 128, 1);           // (8, 32)
    out_gemm_kernel<<<out_grid, 256>>>(Wo, bo, out);
}

// round 7
// speedup vs baseline: 2.4458x; 1.2256x over previous
#include <cuda_runtime.h>
#include <cuda_bf16.h>
#include <cstdint>

#define B_  2
#define S_  2048
#define D_  1024
#define H_  16
#define HD_ 64
#define M_  (B_*S_)   // 4096

// ---------------- device scratch (allocation-free rule) ----------------
__device__ float g_q[B_*H_*S_*HD_];           // [b,h,s,d] fp32
__device__ float g_k[B_*H_*S_*HD_];
__device__ float g_v[B_*H_*S_*HD_];
__device__ __nv_bfloat16 g_x_hi[M_*D_];       // [m][k]
__device__ __nv_bfloat16 g_x_lo[M_*D_];
__device__ __nv_bfloat16 g_att_hi[M_*D_];     // [m][n]  n = h*64+d
__device__ __nv_bfloat16 g_att_lo[M_*D_];
__device__ __nv_bfloat16 g_wt_hi[4*D_*D_];    // [n][k]: rows 0..3071 = Wq^T,Wk^T,Wv^T; 3072.. = Wo^T
__device__ __nv_bfloat16 g_wt_lo[4*D_*D_];
__device__ float g_bias[3*D_];                // concat bq,bk,bv

// ---------------- PTX helpers (feature-free: sm_80-class instructions only) --
__device__ __forceinline__ uint32_t smem_u32(const void* p) {
    uint32_t a;
    asm("{ .reg .u64 t; cvta.to.shared.u64 t, %1; cvt.u32.u64 %0, t; }" : "=r"(a) : "l"(p));
    return a;
}
__device__ __forceinline__ void cp16(uint32_t saddr, const void* g) {
    asm volatile("cp.async.cg.shared.global [%0], [%1], 16;" :: "r"(saddr), "l"(g) : "memory");
}
__device__ __forceinline__ void cp_commit() {
    asm volatile("cp.async.commit_group;" ::: "memory");
}
template <int N>
__device__ __forceinline__ void cp_wait() {
    asm volatile("cp.async.wait_group %0;" :: "n"(N) : "memory");
}
__device__ __forceinline__ void ldsm4(uint32_t& r0, uint32_t& r1, uint32_t& r2, uint32_t& r3,
                                      uint32_t a) {
    asm volatile("ldmatrix.sync.aligned.m8n8.x4.shared.b16 {%0,%1,%2,%3}, [%4];"
                 : "=r"(r0), "=r"(r1), "=r"(r2), "=r"(r3) : "r"(a));
}
__device__ __forceinline__ void mma16816(float* d, const uint32_t* a, const uint32_t* b) {
    asm volatile("mma.sync.aligned.m16n8k16.row.col.f32.bf16.bf16.f32 "
                 "{%0,%1,%2,%3}, {%4,%5,%6,%7}, {%8,%9}, {%0,%1,%2,%3};"
                 : "+f"(d[0]), "+f"(d[1]), "+f"(d[2]), "+f"(d[3])
                 : "r"(a[0]), "r"(a[1]), "r"(a[2]), "r"(a[3]), "r"(b[0]), "r"(b[1]));
}

// ---------------- prep kernels ----------------
__global__ __launch_bounds__(256) void x_prep_kernel(const float* __restrict__ x) {
    int idx = blockIdx.x * 256 + threadIdx.x;          // 1M float4
    float4 v = reinterpret_cast<const float4*>(x)[idx];
    __nv_bfloat16 h0 = __float2bfloat16(v.x), h1 = __float2bfloat16(v.y);
    __nv_bfloat16 h2 = __float2bfloat16(v.z), h3 = __float2bfloat16(v.w);
    __nv_bfloat162 hi0{h0, h1}, hi1{h2, h3};
    __nv_bfloat162 lo0{__float2bfloat16(v.x - __bfloat162float(h0)),
                       __float2bfloat16(v.y - __bfloat162float(h1))};
    __nv_bfloat162 lo1{__float2bfloat16(v.z - __bfloat162float(h2)),
                       __float2bfloat16(v.w - __bfloat162float(h3))};
    reinterpret_cast<__nv_bfloat162*>(g_x_hi)[idx * 2 + 0] = hi0;
    reinterpret_cast<__nv_bfloat162*>(g_x_hi)[idx * 2 + 1] = hi1;
    reinterpret_cast<__nv_bfloat162*>(g_x_lo)[idx * 2 + 0] = lo0;
    reinterpret_cast<__nv_bfloat162*>(g_x_lo)[idx * 2 + 1] = lo1;
}

__global__ __launch_bounds__(256) void w_prep_kernel(const float* __restrict__ Wq,
                                                     const float* __restrict__ Wk,
                                                     const float* __restrict__ Wv,
                                                     const float* __restrict__ Wo) {
    __shared__ float T[32][33];
    int z = blockIdx.z;
    const float* W = (z == 0) ? Wq : (z == 1) ? Wk : (z == 2) ? Wv : Wo;
    int k0 = blockIdx.x * 32, n0 = blockIdx.y * 32;
    int tx = threadIdx.x & 31, ty = threadIdx.x >> 5;   // 32 x 8
    #pragma unroll
    for (int i = 0; i < 4; i++)
        T[ty + 8 * i][tx] = W[(size_t)(k0 + ty + 8 * i) * D_ + n0 + tx];
    __syncthreads();
    #pragma unroll
    for (int i = 0; i < 4; i++) {
        int n = n0 + ty + 8 * i, k = k0 + tx;
        float v = T[tx][ty + 8 * i];
        __nv_bfloat16 hi = __float2bfloat16(v);
        size_t o = (size_t)(z * D_ + n) * D_ + k;
        g_wt_hi[o] = hi;
        g_wt_lo[o] = __float2bfloat16(v - __bfloat162float(hi));
    }
}

__global__ __launch_bounds__(256) void bias_prep_kernel(const float* __restrict__ bq,
                                                        const float* __restrict__ bk,
                                                        const float* __restrict__ bv) {
    int i = blockIdx.x * 256 + threadIdx.x;   // 0..3071
    g_bias[i] = (i < D_) ? bq[i] : (i < 2 * D_) ? bk[i - D_] : bv[i - 2 * D_];
}

// ---------------- HMMA split-bf16 GEMM ----------------
// C[128x128] tile, K=1024, 3 passes (hi*hi, lo*hi, hi*lo), BK=32, cp.async
// double buffer. 8 warps (2x4): warp computes 64 rows x 32 cols via 4x4
// m16n8k16. smem rows padded to 40 bf16 (80B stride -> conflict-free ldmatrix).
#define NCHUNK 96   // 3 passes * 32 k-chunks

__global__ __launch_bounds__(256, 2)
void gemm_hmma_kernel(int src_mode /*0=x,1=att*/, int b_row0,
                      const float* __restrict__ bias, float* __restrict__ outp,
                      int qkv_scatter)
{
    __shared__ __nv_bfloat16 As[2][128][40];
    __shared__ __nv_bfloat16 Bs[2][128][40];

    const int tid = threadIdx.x;
    const int wid = tid >> 5;
    const int lane = tid & 31;
    const int m0 = blockIdx.y * 128;
    const int n0 = blockIdx.x * 128;
    const int wm = wid & 1;          // 0,1: row half (64 rows)
    const int wn = wid >> 1;         // 0..3: 32-col group

    const __nv_bfloat16* a_hi = src_mode ? g_att_hi : g_x_hi;
    const __nv_bfloat16* a_lo = src_mode ? g_att_lo : g_x_lo;

    const int seg = tid & 3;         // 16B segment (8 bf16)
    const int hr  = tid >> 2;        // 0..63

    float acc[4][4][4];
    #pragma unroll
    for (int i = 0; i < 4; i++)
        #pragma unroll
        for (int j = 0; j < 4; j++)
            acc[i][j][0] = acc[i][j][1] = acc[i][j][2] = acc[i][j][3] = 0.f;

    const uint32_t aS0 = smem_u32(&As[0][0][0]);
    const uint32_t bS0 = smem_u32(&Bs[0][0][0]);
    const uint32_t stageBytes = 128 * 40 * 2;   // 10240

    auto issue_load = [&](int c, int st) {
        const int p  = c >> 5;
        const int k0 = (c & 31) * 32;
        const __nv_bfloat16* Asrc = (p == 1) ? a_lo : a_hi;
        const __nv_bfloat16* Bsrc = (p == 2) ? g_wt_lo : g_wt_hi;
        uint32_t sa = aS0 + st * stageBytes + (uint32_t)(hr * 80 + seg * 16);
        uint32_t sb = bS0 + st * stageBytes + (uint32_t)(hr * 80 + seg * 16);
        const __nv_bfloat16* ga = Asrc + (size_t)(m0 + hr) * D_ + k0 + seg * 8;
        const __nv_bfloat16* gb = Bsrc + (size_t)(b_row0 + n0 + hr) * D_ + k0 + seg * 8;
        cp16(sa, ga);
        cp16(sb, gb);
        cp16(sa + 64 * 80, ga + (size_t)64 * D_);
        cp16(sb + 64 * 80, gb + (size_t)64 * D_);
        cp_commit();
    };

    issue_load(0, 0);

    for (int c = 0; c < NCHUNK; ++c) {
        const int st = c & 1;
        if (c + 1 < NCHUNK) {
            issue_load(c + 1, st ^ 1);
            cp_wait<1>();
        } else {
            cp_wait<0>();
        }
        __syncthreads();

        const uint32_t aB = aS0 + st * stageBytes;
        const uint32_t bB = bS0 + st * stageBytes;

        #pragma unroll
        for (int kk = 0; kk < 2; ++kk) {
            uint32_t af[4][4];
            #pragma unroll
            for (int mt = 0; mt < 4; ++mt) {
                int row = wm * 64 + mt * 16 + (lane & 15);
                int sg  = kk * 2 + (lane >> 4);
                ldsm4(af[mt][0], af[mt][1], af[mt][2], af[mt][3],
                      aB + (uint32_t)(row * 80 + sg * 16));
            }
            uint32_t bf[4][2];
            #pragma unroll
            for (int j = 0; j < 2; ++j) {
                int g   = lane >> 3;
                int row = wn * 32 + j * 16 + ((g & 2) ? 8 : 0) + (lane & 7);
                int sg  = kk * 2 + (g & 1);
                uint32_t r0, r1, r2, r3;
                ldsm4(r0, r1, r2, r3, bB + (uint32_t)(row * 80 + sg * 16));
                bf[j * 2 + 0][0] = r0; bf[j * 2 + 0][1] = r1;
                bf[j * 2 + 1][0] = r2; bf[j * 2 + 1][1] = r3;
            }
            #pragma unroll
            for (int mt = 0; mt < 4; ++mt)
                #pragma unroll
                for (int nt = 0; nt < 4; ++nt)
                    mma16816(acc[mt][nt], af[mt], bf[nt]);
        }
        __syncthreads();
    }

    // ---- epilogue: bias add + store (optionally head-major scatter) ----
    #pragma unroll
    for (int nt = 0; nt < 4; ++nt) {
        int ng = n0 + wn * 32 + nt * 8 + (lane & 3) * 2;
        float bx = bias[ng], by = bias[ng + 1];
        float* dbase;
        int doff;
        if (qkv_scatter) {
            int sel = ng >> 10;
            int nl  = ng & (D_ - 1);
            int hh  = nl >> 6;
            int dd  = nl & 63;
            dbase = (sel == 0) ? g_q : (sel == 1) ? g_k : g_v;
            // addr = (((bb*H + hh)*S + ss) * 64 + dd ; bb,ss from row below
            doff = hh;      // stash head; compute per-row
            #pragma unroll
            for (int mt = 0; mt < 4; ++mt) {
                #pragma unroll
                for (int h2 = 0; h2 < 2; ++h2) {
                    int row = m0 + wm * 64 + mt * 16 + (lane >> 2) + h2 * 8;
                    int bb = row >> 11, ss = row & (S_ - 1);
                    float2 v;
                    v.x = acc[mt][nt][h2 * 2 + 0] + bx;
                    v.y = acc[mt][nt][h2 * 2 + 1] + by;
                    *reinterpret_cast<float2*>(
                        dbase + (((size_t)bb * H_ + doff) * S_ + ss) * HD_ + dd) = v;
                }
            }
        } else {
            #pragma unroll
            for (int mt = 0; mt < 4; ++mt) {
                #pragma unroll
                for (int h2 = 0; h2 < 2; ++h2) {
                    int row = m0 + wm * 64 + mt * 16 + (lane >> 2) + h2 * 8;
                    float2 v;
                    v.x = acc[mt][nt][h2 * 2 + 0] + bx;
                    v.y = acc[mt][nt][h2 * 2 + 1] + by;
                    *reinterpret_cast<float2*>(outp + (size_t)row * D_ + ng) = v;
                }
            }
        }
    }
}

// ---------------------------------------------------------------------------
// Flash attention (fp32 SIMT, proven in R3/R4; epilogue emits bf16 hi/lo)
// ---------------------------------------------------------------------------
#define BQ 128
#define BK 64
#define QP 132
#define KP 68
#define ATTN_SMEM ((64*QP + 64*KP + 64*KP) * sizeof(float))

__global__ __launch_bounds__(256)
void attn_kernel()
{
    extern __shared__ float smf[];
    float* Qt = smf;
    float* Kt = smf + 64 * QP;
    float* Vs = smf + 64 * QP + 64 * KP;

    const int tid  = threadIdx.x;
    const int tx   = tid & 15;
    const int ty   = tid >> 4;
    const int lane = tid & 31;
    const int qt = blockIdx.x, h = blockIdx.y, b = blockIdx.z;
    const float scale = 0.125f;

    const float* qp = g_q + (((size_t)b * H_ + h) * S_ + qt * BQ) * HD_;
    const float* kp = g_k + ((size_t)b * H_ + h) * S_ * HD_;
    const float* vp = g_v + ((size_t)b * H_ + h) * S_ * HD_;

    {
        int row = tid & 127;
        int cg  = tid >> 7;
        const float* src = qp + row * HD_ + cg * 32;
        #pragma unroll
        for (int ii = 0; ii < 8; ii++) {
            float4 v = *reinterpret_cast<const float4*>(src + ii * 4);
            int d = cg * 32 + ii * 4;
            Qt[(d + 0) * QP + row] = v.x * scale;
            Qt[(d + 1) * QP + row] = v.y * scale;
            Qt[(d + 2) * QP + row] = v.z * scale;
            Qt[(d + 3) * QP + row] = v.w * scale;
        }
    }

    float m_i[8], l_i[8], o[8][4];
    #pragma unroll
    for (int i = 0; i < 8; i++) {
        m_i[i] = -1e30f; l_i[i] = 0.f;
        o[i][0] = o[i][1] = o[i][2] = o[i][3] = 0.f;
    }

    for (int kt = 0; kt < S_ / BK; ++kt) {
        __syncthreads();
        {
            int row = tid & 63;
            int cg  = tid >> 6;
            const float* ks = kp + (size_t)(kt * BK + row) * HD_ + cg * 16;
            const float* vsrc = vp + (size_t)(kt * BK + row) * HD_ + cg * 16;
            #pragma unroll
            for (int ii = 0; ii < 4; ii++) {
                float4 kv = *reinterpret_cast<const float4*>(ks + ii * 4);
                int d = cg * 16 + ii * 4;
                Kt[(d + 0) * KP + row] = kv.x;
                Kt[(d + 1) * KP + row] = kv.y;
                Kt[(d + 2) * KP + row] = kv.z;
                Kt[(d + 3) * KP + row] = kv.w;
                *reinterpret_cast<float4*>(&Vs[row * KP + cg * 16 + ii * 4]) =
                    *reinterpret_cast<const float4*>(vsrc + ii * 4);
            }
        }
        __syncthreads();

        float s[8][4];
        #pragma unroll
        for (int i = 0; i < 8; i++)
            s[i][0] = s[i][1] = s[i][2] = s[i][3] = 0.f;

        #pragma unroll 8
        for (int d = 0; d < 64; d++) {
            float4 q0 = *reinterpret_cast<const float4*>(&Qt[d * QP + ty * 4]);
            float4 q1 = *reinterpret_cast<const float4*>(&Qt[d * QP + ty * 4 + 64]);
            float4 kv = *reinterpret_cast<const float4*>(&Kt[d * KP + tx * 4]);
            float qa[8] = {q0.x, q0.y, q0.z, q0.w, q1.x, q1.y, q1.z, q1.w};
            #pragma unroll
            for (int i = 0; i < 8; i++) {
                s[i][0] += qa[i] * kv.x;
                s[i][1] += qa[i] * kv.y;
                s[i][2] += qa[i] * kv.z;
                s[i][3] += qa[i] * kv.w;
            }
        }

        #pragma unroll
        for (int i = 0; i < 8; i++) {
            float mx = fmaxf(fmaxf(s[i][0], s[i][1]), fmaxf(s[i][2], s[i][3]));
            mx = fmaxf(mx, __shfl_xor_sync(0xffffffffu, mx, 1));
            mx = fmaxf(mx, __shfl_xor_sync(0xffffffffu, mx, 2));
            mx = fmaxf(mx, __shfl_xor_sync(0xffffffffu, mx, 4));
            mx = fmaxf(mx, __shfl_xor_sync(0xffffffffu, mx, 8));
            float m_new = fmaxf(m_i[i], mx);
            float corr  = __expf(m_i[i] - m_new);
            float ps = 0.f;
            #pragma unroll
            for (int j = 0; j < 4; j++) {
                float p = __expf(s[i][j] - m_new);
                s[i][j] = p;
                ps += p;
            }
            ps += __shfl_xor_sync(0xffffffffu, ps, 1);
            ps += __shfl_xor_sync(0xffffffffu, ps, 2);
            ps += __shfl_xor_sync(0xffffffffu, ps, 4);
            ps += __shfl_xor_sync(0xffffffffu, ps, 8);
            l_i[i] = l_i[i] * corr + ps;
            m_i[i] = m_new;
            o[i][0] *= corr; o[i][1] *= corr; o[i][2] *= corr; o[i][3] *= corr;
        }

        #pragma unroll 4
        for (int c = 0; c < 64; c++) {
            int src = (lane & 16) | (c >> 2);
            float4 vv = *reinterpret_cast<const float4*>(&Vs[c * KP + tx * 4]);
            #pragma unroll
            for (int i = 0; i < 8; i++) {
                float pv = __shfl_sync(0xffffffffu, s[i][c & 3], src);
                o[i][0] += pv * vv.x;
                o[i][1] += pv * vv.y;
                o[i][2] += pv * vv.z;
                o[i][3] += pv * vv.w;
            }
        }
    }

    // epilogue: normalize -> split bf16 hi/lo into g_att_{hi,lo}[m][h*64+dv]
    #pragma unroll
    for (int i = 0; i < 8; i++) {
        int r = ty * 4 + (i & 3) + (i >> 2) * 64;
        float inv = 1.f / l_i[i];
        size_t idx = ((size_t)b * S_ + qt * BQ + r) * D_ + h * HD_ + tx * 4;
        float v0 = o[i][0] * inv, v1 = o[i][1] * inv, v2 = o[i][2] * inv, v3 = o[i][3] * inv;
        __nv_bfloat16 h0 = __float2bfloat16(v0), h1 = __float2bfloat16(v1);
        __nv_bfloat16 h2 = __float2bfloat16(v2), h3 = __float2bfloat16(v3);
        __nv_bfloat162 hi0{h0, h1}, hi1{h2, h3};
        __nv_bfloat162 lo0{__float2bfloat16(v0 - __bfloat162float(h0)),
                           __float2bfloat16(v1 - __bfloat162float(h1))};
        __nv_bfloat162 lo1{__float2bfloat16(v2 - __bfloat162float(h2)),
                           __float2bfloat16(v3 - __bfloat162float(h3))};
        reinterpret_cast<__nv_bfloat162*>(g_att_hi + idx)[0] = hi0;
        reinterpret_cast<__nv_bfloat162*>(g_att_hi + idx)[1] = hi1;
        reinterpret_cast<__nv_bfloat162*>(g_att_lo + idx)[0] = lo0;
        reinterpret_cast<__nv_bfloat162*>(g_att_lo + idx)[1] = lo1;
    }
}

// ---------------------------------------------------------------------------
extern "C" void kernel_launch(void* const* d_in, const int* in_sizes, int n_in,
                              void* d_out, int out_size)
{
    const float* x  = (const float*)d_in[0];
    const float* Wq = (const float*)d_in[1];
    const float* bq = (const float*)d_in[2];
    const float* Wk = (const float*)d_in[3];
    const float* bk = (const float*)d_in[4];
    const float* Wv = (const float*)d_in[5];
    const float* bv = (const float*)d_in[6];
    const float* Wo = (const float*)d_in[7];
    const float* bo = (const float*)d_in[8];
    float* out = (float*)d_out;

    cudaFuncSetAttribute(attn_kernel, cudaFuncAttributeMaxDynamicSharedMemorySize, (int)ATTN_SMEM);

    // prep
    x_prep_kernel<<<M_ * D_ / 4 / 256, 256>>>(x);
    dim3 wgrid(D_ / 32, D_ / 32, 4);
    w_prep_kernel<<<wgrid, 256>>>(Wq, Wk, Wv, Wo);
    bias_prep_kernel<<<3 * D_ / 256, 256>>>(bq, bk, bv);

    // QKV projection: C[4096 x 3072]
    dim3 qkv_grid(3 * D_ / 128, M_ / 128);
    gemm_hmma_kernel<<<qkv_grid, 256>>>(0, 0, g_bias, nullptr, 1);

    // attention
    dim3 attn_grid(S_ / BQ, H_, B_);
    attn_kernel<<<attn_grid, 256, ATTN_SMEM>>>();

    // output projection: C[4096 x 1024]
    dim3 out_grid(D_ / 128, M_ / 128);
    gemm_hmma_kernel<<<out_grid, 256>>>(1, 3 * D_, bo, out, 0);
}

// round 11
// speedup vs baseline: 3.9800x; 1.6273x over previous
#include <cuda_runtime.h>
#include <cuda_bf16.h>
#include <cstdint>

#define B_  2
#define S_  2048
#define D_  1024
#define H_  16
#define HD_ 64
#define M_  (B_*S_)   // 4096

// ---------------- device scratch (allocation-free rule) ----------------
__device__ __nv_bfloat16 g_qhi[B_*H_*S_*HD_];  // [b,h,s,d] split bf16 (scale folded)
__device__ __nv_bfloat16 g_qlo[B_*H_*S_*HD_];
__device__ __nv_bfloat16 g_khi[B_*H_*S_*HD_];
__device__ __nv_bfloat16 g_klo[B_*H_*S_*HD_];
__device__ __nv_bfloat16 g_vhi[B_*H_*S_*HD_];
__device__ __nv_bfloat16 g_vlo[B_*H_*S_*HD_];
__device__ __nv_bfloat16 g_x_hi[M_*D_];        // [m][k]
__device__ __nv_bfloat16 g_x_lo[M_*D_];
__device__ __nv_bfloat16 g_att_hi[M_*D_];      // [m][n]  n = h*64+d
__device__ __nv_bfloat16 g_att_lo[M_*D_];
__device__ __nv_bfloat16 g_wt_hi[4*D_*D_];     // [n][k]
__device__ __nv_bfloat16 g_wt_lo[4*D_*D_];
__device__ float g_bias[3*D_];

// ---------------- PTX helpers (feature-free, sm_80-class) ----------------
__device__ __forceinline__ uint32_t smem_u32(const void* p) {
    uint32_t a;
    asm("{ .reg .u64 t; cvta.to.shared.u64 t, %1; cvt.u32.u64 %0, t; }" : "=r"(a) : "l"(p));
    return a;
}
__device__ __forceinline__ void cp16(uint32_t saddr, const void* g) {
    asm volatile("cp.async.cg.shared.global [%0], [%1], 16;" :: "r"(saddr), "l"(g) : "memory");
}
__device__ __forceinline__ void cp_commit() {
    asm volatile("cp.async.commit_group;" ::: "memory");
}
template <int N>
__device__ __forceinline__ void cp_wait() {
    asm volatile("cp.async.wait_group %0;" :: "n"(N) : "memory");
}
__device__ __forceinline__ void ldsm4(uint32_t& r0, uint32_t& r1, uint32_t& r2, uint32_t& r3,
                                      uint32_t a) {
    asm volatile("ldmatrix.sync.aligned.m8n8.x4.shared.b16 {%0,%1,%2,%3}, [%4];"
                 : "=r"(r0), "=r"(r1), "=r"(r2), "=r"(r3) : "r"(a));
}
__device__ __forceinline__ void ldsm4t(uint32_t& r0, uint32_t& r1, uint32_t& r2, uint32_t& r3,
                                       uint32_t a) {
    asm volatile("ldmatrix.sync.aligned.m8n8.x4.trans.shared.b16 {%0,%1,%2,%3}, [%4];"
                 : "=r"(r0), "=r"(r1), "=r"(r2), "=r"(r3) : "r"(a));
}
__device__ __forceinline__ void mma16816(float* d, const uint32_t* a, const uint32_t* b) {
    asm volatile("mma.sync.aligned.m16n8k16.row.col.f32.bf16.bf16.f32 "
                 "{%0,%1,%2,%3}, {%4,%5,%6,%7}, {%8,%9}, {%0,%1,%2,%3};"
                 : "+f"(d[0]), "+f"(d[1]), "+f"(d[2]), "+f"(d[3])
                 : "r"(a[0]), "r"(a[1]), "r"(a[2]), "r"(a[3]), "r"(b[0]), "r"(b[1]));
}
__device__ __forceinline__ uint32_t pack_hi(float a, float b) {
    __nv_bfloat162 t = __floats2bfloat162_rn(a, b);
    return *reinterpret_cast<uint32_t*>(&t);
}
__device__ __forceinline__ uint32_t pack_lo_res(float a, float b) {
    float ra = a - __bfloat162float(__float2bfloat16(a));
    float rb = b - __bfloat162float(__float2bfloat16(b));
    __nv_bfloat162 t = __floats2bfloat162_rn(ra, rb);
    return *reinterpret_cast<uint32_t*>(&t);
}

// ---------------- prep kernels ----------------
__global__ __launch_bounds__(256) void x_prep_kernel(const float* __restrict__ x) {
    int idx = blockIdx.x * 256 + threadIdx.x;
    float4 v = reinterpret_cast<const float4*>(x)[idx];
    __nv_bfloat16 h0 = __float2bfloat16(v.x), h1 = __float2bfloat16(v.y);
    __nv_bfloat16 h2 = __float2bfloat16(v.z), h3 = __float2bfloat16(v.w);
    __nv_bfloat162 hi0{h0, h1}, hi1{h2, h3};
    __nv_bfloat162 lo0{__float2bfloat16(v.x - __bfloat162float(h0)),
                       __float2bfloat16(v.y - __bfloat162float(h1))};
    __nv_bfloat162 lo1{__float2bfloat16(v.z - __bfloat162float(h2)),
                       __float2bfloat16(v.w - __bfloat162float(h3))};
    reinterpret_cast<__nv_bfloat162*>(g_x_hi)[idx * 2 + 0] = hi0;
    reinterpret_cast<__nv_bfloat162*>(g_x_hi)[idx * 2 + 1] = hi1;
    reinterpret_cast<__nv_bfloat162*>(g_x_lo)[idx * 2 + 0] = lo0;
    reinterpret_cast<__nv_bfloat162*>(g_x_lo)[idx * 2 + 1] = lo1;
}

__global__ __launch_bounds__(256) void w_prep_kernel(const float* __restrict__ Wq,
                                                     const float* __restrict__ Wk,
                                                     const float* __restrict__ Wv,
                                                     const float* __restrict__ Wo) {
    __shared__ float T[32][33];
    int z = blockIdx.z;
    const float* W = (z == 0) ? Wq : (z == 1) ? Wk : (z == 2) ? Wv : Wo;
    int k0 = blockIdx.x * 32, n0 = blockIdx.y * 32;
    int tx = threadIdx.x & 31, ty = threadIdx.x >> 5;
    #pragma unroll
    for (int i = 0; i < 4; i++)
        T[ty + 8 * i][tx] = W[(size_t)(k0 + ty + 8 * i) * D_ + n0 + tx];
    __syncthreads();
    #pragma unroll
    for (int i = 0; i < 4; i++) {
        int n = n0 + ty + 8 * i, k = k0 + tx;
        float v = T[tx][ty + 8 * i];
        __nv_bfloat16 hi = __float2bfloat16(v);
        size_t o = (size_t)(z * D_ + n) * D_ + k;
        g_wt_hi[o] = hi;
        g_wt_lo[o] = __float2bfloat16(v - __bfloat162float(hi));
    }
}

__global__ __launch_bounds__(256) void bias_prep_kernel(const float* __restrict__ bq,
                                                        const float* __restrict__ bk,
                                                        const float* __restrict__ bv) {
    int i = blockIdx.x * 256 + threadIdx.x;
    g_bias[i] = (i < D_) ? bq[i] : (i < 2 * D_) ? bk[i - D_] : bv[i - 2 * D_];
}

// ---------------- HMMA split-bf16 GEMM (from R7; epilogue now emits split bf16 qkv)
#define NCHUNK 96

__global__ __launch_bounds__(256, 2)
void gemm_hmma_kernel(int src_mode, int b_row0,
                      const float* __restrict__ bias, float* __restrict__ outp,
                      int qkv_scatter)
{
    __shared__ __nv_bfloat16 As[2][128][40];
    __shared__ __nv_bfloat16 Bs[2][128][40];

    const int tid = threadIdx.x;
    const int wid = tid >> 5;
    const int lane = tid & 31;
    const int m0 = blockIdx.y * 128;
    const int n0 = blockIdx.x * 128;
    const int wm = wid & 1;
    const int wn = wid >> 1;

    const __nv_bfloat16* a_hi = src_mode ? g_att_hi : g_x_hi;
    const __nv_bfloat16* a_lo = src_mode ? g_att_lo : g_x_lo;

    const int seg = tid & 3;
    const int hr  = tid >> 2;

    float acc[4][4][4];
    #pragma unroll
    for (int i = 0; i < 4; i++)
        #pragma unroll
        for (int j = 0; j < 4; j++)
            acc[i][j][0] = acc[i][j][1] = acc[i][j][2] = acc[i][j][3] = 0.f;

    const uint32_t aS0 = smem_u32(&As[0][0][0]);
    const uint32_t bS0 = smem_u32(&Bs[0][0][0]);
    const uint32_t stageBytes = 128 * 40 * 2;

    auto issue_load = [&](int c, int st) {
        const int p  = c >> 5;
        const int k0 = (c & 31) * 32;
        const __nv_bfloat16* Asrc = (p == 1) ? a_lo : a_hi;
        const __nv_bfloat16* Bsrc = (p == 2) ? g_wt_lo : g_wt_hi;
        uint32_t sa = aS0 + st * stageBytes + (uint32_t)(hr * 80 + seg * 16);
        uint32_t sb = bS0 + st * stageBytes + (uint32_t)(hr * 80 + seg * 16);
        const __nv_bfloat16* ga = Asrc + (size_t)(m0 + hr) * D_ + k0 + seg * 8;
        const __nv_bfloat16* gb = Bsrc + (size_t)(b_row0 + n0 + hr) * D_ + k0 + seg * 8;
        cp16(sa, ga);
        cp16(sb, gb);
        cp16(sa + 64 * 80, ga + (size_t)64 * D_);
        cp16(sb + 64 * 80, gb + (size_t)64 * D_);
        cp_commit();
    };

    issue_load(0, 0);

    for (int c = 0; c < NCHUNK; ++c) {
        const int st = c & 1;
        if (c + 1 < NCHUNK) {
            issue_load(c + 1, st ^ 1);
            cp_wait<1>();
        } else {
            cp_wait<0>();
        }
        __syncthreads();

        const uint32_t aB = aS0 + st * stageBytes;
        const uint32_t bB = bS0 + st * stageBytes;

        #pragma unroll
        for (int kk = 0; kk < 2; ++kk) {
            uint32_t af[4][4];
            #pragma unroll
            for (int mt = 0; mt < 4; ++mt) {
                int row = wm * 64 + mt * 16 + (lane & 15);
                int sg  = kk * 2 + (lane >> 4);
                ldsm4(af[mt][0], af[mt][1], af[mt][2], af[mt][3],
                      aB + (uint32_t)(row * 80 + sg * 16));
            }
            uint32_t bf[4][2];
            #pragma unroll
            for (int j = 0; j < 2; ++j) {
                int g   = lane >> 3;
                int row = wn * 32 + j * 16 + ((g & 2) ? 8 : 0) + (lane & 7);
                int sg  = kk * 2 + (g & 1);
                uint32_t r0, r1, r2, r3;
                ldsm4(r0, r1, r2, r3, bB + (uint32_t)(row * 80 + sg * 16));
                bf[j * 2 + 0][0] = r0; bf[j * 2 + 0][1] = r1;
                bf[j * 2 + 1][0] = r2; bf[j * 2 + 1][1] = r3;
            }
            #pragma unroll
            for (int mt = 0; mt < 4; ++mt)
                #pragma unroll
                for (int nt = 0; nt < 4; ++nt)
                    mma16816(acc[mt][nt], af[mt], bf[nt]);
        }
        __syncthreads();
    }

    // ---- epilogue ----
    #pragma unroll
    for (int nt = 0; nt < 4; ++nt) {
        int ng = n0 + wn * 32 + nt * 8 + (lane & 3) * 2;
        float bx = bias[ng], by = bias[ng + 1];
        if (qkv_scatter) {
            int sel = ng >> 10;
            int nl  = ng & (D_ - 1);
            int hh  = nl >> 6;
            int dd  = nl & 63;
            float scale = (sel == 0) ? 0.125f : 1.0f;
            __nv_bfloat16* dh = (sel == 0) ? g_qhi : (sel == 1) ? g_khi : g_vhi;
            __nv_bfloat16* dl = (sel == 0) ? g_qlo : (sel == 1) ? g_klo : g_vlo;
            #pragma unroll
            for (int mt = 0; mt < 4; ++mt) {
                #pragma unroll
                for (int h2 = 0; h2 < 2; ++h2) {
                    int row = m0 + wm * 64 + mt * 16 + (lane >> 2) + h2 * 8;
                    int bb = row >> 11, ss = row & (S_ - 1);
                    float vx = (acc[mt][nt][h2 * 2 + 0] + bx) * scale;
                    float vy = (acc[mt][nt][h2 * 2 + 1] + by) * scale;
                    size_t idx = (((size_t)bb * H_ + hh) * S_ + ss) * HD_ + dd;
                    uint32_t hi = pack_hi(vx, vy);
                    uint32_t lo = pack_lo_res(vx, vy);
                    *reinterpret_cast<uint32_t*>(dh + idx) = hi;
                    *reinterpret_cast<uint32_t*>(dl + idx) = lo;
                }
            }
        } else {
            #pragma unroll
            for (int mt = 0; mt < 4; ++mt) {
                #pragma unroll
                for (int h2 = 0; h2 < 2; ++h2) {
                    int row = m0 + wm * 64 + mt * 16 + (lane >> 2) + h2 * 8;
                    float2 v;
                    v.x = acc[mt][nt][h2 * 2 + 0] + bx;
                    v.y = acc[mt][nt][h2 * 2 + 1] + by;
                    *reinterpret_cast<float2*>(outp + (size_t)row * D_ + ng) = v;
                }
            }
        }
    }
}

// ---------------------------------------------------------------------------
// HMMA flash attention. 256 thr / 8 warps; warp owns 16 q-rows; BQ=128, BK=64.
// Split bf16: S = Qh*Kh + Ql*Kh + Qh*Kl ; O += Ph*Vh + Ph*Vl + Pl*Vh.
// smem (bytes): Qhi[128][72]@0 (18432), Qlo@18432, stage st@36864+st*36864:
//   Khi 9216 | Klo 9216 | Vhi 9216 | Vlo 9216.  Row stride 144B.
// ---------------------------------------------------------------------------
#define ATT_SMEM 110592

__global__ __launch_bounds__(256, 2)
void attn_hmma_kernel()
{
    extern __shared__ char smc[];
    const uint32_t sb = smem_u32(smc);
    const int tid  = threadIdx.x;
    const int lane = tid & 31;
    const int wid  = tid >> 5;
    const int q0   = wid * 16;
    const int qt = blockIdx.x, h = blockIdx.y, b = blockIdx.z;

    const __nv_bfloat16* gqh = g_qhi + (((size_t)b * H_ + h) * S_ + qt * 128) * HD_;
    const __nv_bfloat16* gql = g_qlo + (((size_t)b * H_ + h) * S_ + qt * 128) * HD_;
    const __nv_bfloat16* gkh = g_khi + ((size_t)b * H_ + h) * S_ * HD_;
    const __nv_bfloat16* gkl = g_klo + ((size_t)b * H_ + h) * S_ * HD_;
    const __nv_bfloat16* gvh = g_vhi + ((size_t)b * H_ + h) * S_ * HD_;
    const __nv_bfloat16* gvl = g_vlo + ((size_t)b * H_ + h) * S_ * HD_;

    // Q tiles -> smem (group 0)
    {
        int r  = tid >> 1;
        int s4 = (tid & 1) * 4;
        const __nv_bfloat16* sh = gqh + (size_t)r * HD_ + s4 * 8;
        const __nv_bfloat16* sl = gql + (size_t)r * HD_ + s4 * 8;
        uint32_t dh = sb + r * 144 + s4 * 16;
        uint32_t dl = sb + 18432 + r * 144 + s4 * 16;
        #pragma unroll
        for (int i = 0; i < 4; i++) {
            cp16(dh + i * 16, sh + i * 8);
            cp16(dl + i * 16, sl + i * 8);
        }
        cp_commit();
    }

    auto issue_kv = [&](int c, int st) {
        int r  = tid >> 2;
        int sg = (tid & 3) * 2;
        size_t go = (size_t)(c * 64 + r) * HD_ + sg * 8;
        uint32_t sd = sb + 36864 + st * 36864 + r * 144 + sg * 16;
        cp16(sd,              gkh + go); cp16(sd + 16,              gkh + go + 8);
        cp16(sd + 9216,       gkl + go); cp16(sd + 9216 + 16,       gkl + go + 8);
        cp16(sd + 18432,      gvh + go); cp16(sd + 18432 + 16,      gvh + go + 8);
        cp16(sd + 27648,      gvl + go); cp16(sd + 27648 + 16,      gvl + go + 8);
        cp_commit();
    };

    issue_kv(0, 0);

    float o[8][4];
    #pragma unroll
    for (int n = 0; n < 8; n++)
        o[n][0] = o[n][1] = o[n][2] = o[n][3] = 0.f;
    float mA = -1e30f, mB = -1e30f, lA = 0.f, lB = 0.f;

    const uint32_t qhb = sb, qlb = sb + 18432;
    const uint32_t a_row_off = (uint32_t)(q0 + (lane & 15)) * 144 + (lane >> 4) * 16;
    const uint32_t k_row_off = (uint32_t)(lane & 15) * 144 + (lane >> 4) * 16;
    const uint32_t v_row_off = (uint32_t)(lane & 15) * 144 + (lane >> 4) * 16;

    for (int c = 0; c < S_ / 64; ++c) {
        const int st = c & 1;
        if (c + 1 < S_ / 64) {
            issue_kv(c + 1, st ^ 1);
            cp_wait<1>();
        } else {
            cp_wait<0>();
        }
        __syncthreads();

        const uint32_t kbh = sb + 36864 + st * 36864;
        const uint32_t kbl = kbh + 9216;
        const uint32_t vbh = kbh + 18432;
        const uint32_t vbl = kbh + 27648;

        float s[8][4];
        #pragma unroll
        for (int n = 0; n < 8; n++)
            s[n][0] = s[n][1] = s[n][2] = s[n][3] = 0.f;

        // ---- scores: 3 passes ----
        #pragma unroll
        for (int p = 0; p < 3; p++) {
            const uint32_t qb = (p == 1) ? qlb : qhb;
            const uint32_t kb = (p == 2) ? kbl : kbh;
            #pragma unroll
            for (int kk = 0; kk < 4; kk++) {
                uint32_t a[4];
                ldsm4(a[0], a[1], a[2], a[3], qb + a_row_off + kk * 32);
                #pragma unroll
                for (int g = 0; g < 4; g++) {
                    uint32_t r0, r1, r2, r3;
                    ldsm4(r0, r1, r2, r3, kb + k_row_off + (uint32_t)g * 16 * 144 + kk * 32);
                    uint32_t b0[2] = {r0, r2}, b1[2] = {r1, r3};
                    mma16816(s[2 * g],     a, b0);
                    mma16816(s[2 * g + 1], a, b1);
                }
            }
        }

        // ---- online softmax (rows ra = lane>>2, rb = ra+8 of warp tile) ----
        float mxA = -1e30f, mxB = -1e30f;
        #pragma unroll
        for (int n = 0; n < 8; n++) {
            mxA = fmaxf(mxA, fmaxf(s[n][0], s[n][1]));
            mxB = fmaxf(mxB, fmaxf(s[n][2], s[n][3]));
        }
        mxA = fmaxf(mxA, __shfl_xor_sync(0xffffffffu, mxA, 1));
        mxA = fmaxf(mxA, __shfl_xor_sync(0xffffffffu, mxA, 2));
        mxB = fmaxf(mxB, __shfl_xor_sync(0xffffffffu, mxB, 1));
        mxB = fmaxf(mxB, __shfl_xor_sync(0xffffffffu, mxB, 2));
        float mnA = fmaxf(mA, mxA), mnB = fmaxf(mB, mxB);
        float cA = __expf(mA - mnA), cB = __expf(mB - mnB);
        float psA = 0.f, psB = 0.f;
        #pragma unroll
        for (int n = 0; n < 8; n++) {
            s[n][0] = __expf(s[n][0] - mnA); psA += s[n][0];
            s[n][1] = __expf(s[n][1] - mnA); psA += s[n][1];
            s[n][2] = __expf(s[n][2] - mnB); psB += s[n][2];
            s[n][3] = __expf(s[n][3] - mnB); psB += s[n][3];
        }
        psA += __shfl_xor_sync(0xffffffffu, psA, 1);
        psA += __shfl_xor_sync(0xffffffffu, psA, 2);
        psB += __shfl_xor_sync(0xffffffffu, psB, 1);
        psB += __shfl_xor_sync(0xffffffffu, psB, 2);
        lA = lA * cA + psA; lB = lB * cB + psB;
        mA = mnA; mB = mnB;
        #pragma unroll
        for (int n = 0; n < 8; n++) {
            o[n][0] *= cA; o[n][1] *= cA; o[n][2] *= cB; o[n][3] *= cB;
        }

        // ---- P hi fragments (A-operand layout), cached for 2 passes ----
        uint32_t phi[4][4];
        #pragma unroll
        for (int kk = 0; kk < 4; kk++) {
            phi[kk][0] = pack_hi(s[2 * kk][0],     s[2 * kk][1]);
            phi[kk][1] = pack_hi(s[2 * kk][2],     s[2 * kk][3]);
            phi[kk][2] = pack_hi(s[2 * kk + 1][0], s[2 * kk + 1][1]);
            phi[kk][3] = pack_hi(s[2 * kk + 1][2], s[2 * kk + 1][3]);
        }

        // ---- PV pass 1: Phi x Vhi, pass 2: Phi x Vlo ----
        #pragma unroll
        for (int p = 0; p < 2; p++) {
            const uint32_t vb = p ? vbl : vbh;
            #pragma unroll
            for (int kk = 0; kk < 4; kk++) {
                #pragma unroll
                for (int g = 0; g < 4; g++) {
                    uint32_t r0, r1, r2, r3;
                    ldsm4t(r0, r1, r2, r3,
                           vb + v_row_off + (uint32_t)kk * 16 * 144 + g * 32);
                    uint32_t b0[2] = {r0, r1}, b1[2] = {r2, r3};
                    mma16816(o[2 * g],     phi[kk], b0);
                    mma16816(o[2 * g + 1], phi[kk], b1);
                }
            }
        }
        // ---- PV pass 3: Plo x Vhi ----
        #pragma unroll
        for (int kk = 0; kk < 4; kk++) {
            uint32_t pl[4];
            pl[0] = pack_lo_res(s[2 * kk][0],     s[2 * kk][1]);
            pl[1] = pack_lo_res(s[2 * kk][2],     s[2 * kk][3]);
            pl[2] = pack_lo_res(s[2 * kk + 1][0], s[2 * kk + 1][1]);
            pl[3] = pack_lo_res(s[2 * kk + 1][2], s[2 * kk + 1][3]);
            #pragma unroll
            for (int g = 0; g < 4; g++) {
                uint32_t r0, r1, r2, r3;
                ldsm4t(r0, r1, r2, r3,
                       vbh + v_row_off + (uint32_t)kk * 16 * 144 + g * 32);
                uint32_t b0[2] = {r0, r1}, b1[2] = {r2, r3};
                mma16816(o[2 * g],     pl, b0);
                mma16816(o[2 * g + 1], pl, b1);
            }
        }
        __syncthreads();
    }

    // ---- epilogue: normalize, split bf16 hi/lo into g_att ----
    float invA = 1.f / lA, invB = 1.f / lB;
    int rowA = qt * 128 + q0 + (lane >> 2);
    int rowB = rowA + 8;
    size_t baseA = ((size_t)b * S_ + rowA) * D_ + h * HD_ + (lane & 3) * 2;
    size_t baseB = ((size_t)b * S_ + rowB) * D_ + h * HD_ + (lane & 3) * 2;
    #pragma unroll
    for (int n = 0; n < 8; n++) {
        float ax = o[n][0] * invA, ay = o[n][1] * invA;
        float bx = o[n][2] * invB, by = o[n][3] * invB;
        *reinterpret_cast<uint32_t*>(g_att_hi + baseA + n * 8) = pack_hi(ax, ay);
        *reinterpret_cast<uint32_t*>(g_att_lo + baseA + n * 8) = pack_lo_res(ax, ay);
        *reinterpret_cast<uint32_t*>(g_att_hi + baseB + n * 8) = pack_hi(bx, by);
        *reinterpret_cast<uint32_t*>(g_att_lo + baseB + n * 8) = pack_lo_res(bx, by);
    }
}

// ---------------------------------------------------------------------------
extern "C" void kernel_launch(void* const* d_in, const int* in_sizes, int n_in,
                              void* d_out, int out_size)
{
    const float* x  = (const float*)d_in[0];
    const float* Wq = (const float*)d_in[1];
    const float* bq = (const float*)d_in[2];
    const float* Wk = (const float*)d_in[3];
    const float* bk = (const float*)d_in[4];
    const float* Wv = (const float*)d_in[5];
    const float* bv = (const float*)d_in[6];
    const float* Wo = (const float*)d_in[7];
    const float* bo = (const float*)d_in[8];
    float* out = (float*)d_out;

    cudaFuncSetAttribute(attn_hmma_kernel, cudaFuncAttributeMaxDynamicSharedMemorySize, ATT_SMEM);

    // prep
    x_prep_kernel<<<M_ * D_ / 4 / 256, 256>>>(x);
    dim3 wgrid(D_ / 32, D_ / 32, 4);
    w_prep_kernel<<<wgrid, 256>>>(Wq, Wk, Wv, Wo);
    bias_prep_kernel<<<3 * D_ / 256, 256>>>(bq, bk, bv);

    // QKV projection: C[4096 x 3072] -> split bf16 q/k/v (head-major)
    dim3 qkv_grid(3 * D_ / 128, M_ / 128);
    gemm_hmma_kernel<<<qkv_grid, 256>>>(0, 0, g_bias, nullptr, 1);

    // attention
    dim3 attn_grid(S_ / 128, H_, B_);
    attn_hmma_kernel<<<attn_grid, 256, ATT_SMEM>>>();

    // output projection: C[4096 x 1024]
    dim3 out_grid(D_ / 128, M_ / 128);
    gemm_hmma_kernel<<<out_grid, 256>>>(1, 3 * D_, bo, out, 0);
}

// round 12
// speedup vs baseline: 5.4631x; 1.3726x over previous
#include <cuda_runtime.h>
#include <cuda_bf16.h>
#include <cstdint>

#define B_  2
#define S_  2048
#define D_  1024
#define H_  16
#define HD_ 64
#define M_  (B_*S_)   // 4096

// ---------------- device scratch (allocation-free rule) ----------------
__device__ __nv_bfloat16 g_qhi[B_*H_*S_*HD_];  // [b,h,s,d] split bf16 (scale*log2e folded)
__device__ __nv_bfloat16 g_qlo[B_*H_*S_*HD_];
__device__ __nv_bfloat16 g_khi[B_*H_*S_*HD_];
__device__ __nv_bfloat16 g_klo[B_*H_*S_*HD_];
__device__ __nv_bfloat16 g_vhi[B_*H_*S_*HD_];
__device__ __nv_bfloat16 g_vlo[B_*H_*S_*HD_];
__device__ __nv_bfloat16 g_x_hi[M_*D_];        // [m][k]
__device__ __nv_bfloat16 g_x_lo[M_*D_];
__device__ __nv_bfloat16 g_att_hi[M_*D_];      // [m][n]  n = h*64+d
__device__ __nv_bfloat16 g_att_lo[M_*D_];
__device__ __nv_bfloat16 g_wt_hi[4*D_*D_];     // [n][k]
__device__ __nv_bfloat16 g_wt_lo[4*D_*D_];
__device__ float g_bias[3*D_];

// ---------------- PTX helpers (feature-free, sm_80-class) ----------------
__device__ __forceinline__ uint32_t smem_u32(const void* p) {
    uint32_t a;
    asm("{ .reg .u64 t; cvta.to.shared.u64 t, %1; cvt.u32.u64 %0, t; }" : "=r"(a) : "l"(p));
    return a;
}
__device__ __forceinline__ void cp16(uint32_t saddr, const void* g) {
    asm volatile("cp.async.cg.shared.global [%0], [%1], 16;" :: "r"(saddr), "l"(g) : "memory");
}
__device__ __forceinline__ void cp_commit() {
    asm volatile("cp.async.commit_group;" ::: "memory");
}
template <int N>
__device__ __forceinline__ void cp_wait() {
    asm volatile("cp.async.wait_group %0;" :: "n"(N) : "memory");
}
__device__ __forceinline__ void ldsm4(uint32_t& r0, uint32_t& r1, uint32_t& r2, uint32_t& r3,
                                      uint32_t a) {
    asm volatile("ldmatrix.sync.aligned.m8n8.x4.shared.b16 {%0,%1,%2,%3}, [%4];"
                 : "=r"(r0), "=r"(r1), "=r"(r2), "=r"(r3) : "r"(a));
}
__device__ __forceinline__ void ldsm4t(uint32_t& r0, uint32_t& r1, uint32_t& r2, uint32_t& r3,
                                       uint32_t a) {
    asm volatile("ldmatrix.sync.aligned.m8n8.x4.trans.shared.b16 {%0,%1,%2,%3}, [%4];"
                 : "=r"(r0), "=r"(r1), "=r"(r2), "=r"(r3) : "r"(a));
}
__device__ __forceinline__ void mma16816(float* d, const uint32_t* a, const uint32_t* b) {
    asm volatile("mma.sync.aligned.m16n8k16.row.col.f32.bf16.bf16.f32 "
                 "{%0,%1,%2,%3}, {%4,%5,%6,%7}, {%8,%9}, {%0,%1,%2,%3};"
                 : "+f"(d[0]), "+f"(d[1]), "+f"(d[2]), "+f"(d[3])
                 : "r"(a[0]), "r"(a[1]), "r"(a[2]), "r"(a[3]), "r"(b[0]), "r"(b[1]));
}
__device__ __forceinline__ uint32_t pack_hi(float a, float b) {
    __nv_bfloat162 t = __floats2bfloat162_rn(a, b);
    return *reinterpret_cast<uint32_t*>(&t);
}
__device__ __forceinline__ uint32_t pack_lo_res(float a, float b) {
    float ra = a - __bfloat162float(__float2bfloat16(a));
    float rb = b - __bfloat162float(__float2bfloat16(b));
    __nv_bfloat162 t = __floats2bfloat162_rn(ra, rb);
    return *reinterpret_cast<uint32_t*>(&t);
}

// ---------------- prep kernels ----------------
__global__ __launch_bounds__(256) void x_prep_kernel(const float* __restrict__ x) {
    int idx = blockIdx.x * 256 + threadIdx.x;
    float4 v = reinterpret_cast<const float4*>(x)[idx];
    __nv_bfloat16 h0 = __float2bfloat16(v.x), h1 = __float2bfloat16(v.y);
    __nv_bfloat16 h2 = __float2bfloat16(v.z), h3 = __float2bfloat16(v.w);
    __nv_bfloat162 hi0{h0, h1}, hi1{h2, h3};
    __nv_bfloat162 lo0{__float2bfloat16(v.x - __bfloat162float(h0)),
                       __float2bfloat16(v.y - __bfloat162float(h1))};
    __nv_bfloat162 lo1{__float2bfloat16(v.z - __bfloat162float(h2)),
                       __float2bfloat16(v.w - __bfloat162float(h3))};
    reinterpret_cast<__nv_bfloat162*>(g_x_hi)[idx * 2 + 0] = hi0;
    reinterpret_cast<__nv_bfloat162*>(g_x_hi)[idx * 2 + 1] = hi1;
    reinterpret_cast<__nv_bfloat162*>(g_x_lo)[idx * 2 + 0] = lo0;
    reinterpret_cast<__nv_bfloat162*>(g_x_lo)[idx * 2 + 1] = lo1;
}

__global__ __launch_bounds__(256) void w_prep_kernel(const float* __restrict__ Wq,
                                                     const float* __restrict__ Wk,
                                                     const float* __restrict__ Wv,
                                                     const float* __restrict__ Wo) {
    __shared__ float T[32][33];
    int z = blockIdx.z;
    const float* W = (z == 0) ? Wq : (z == 1) ? Wk : (z == 2) ? Wv : Wo;
    int k0 = blockIdx.x * 32, n0 = blockIdx.y * 32;
    int tx = threadIdx.x & 31, ty = threadIdx.x >> 5;
    #pragma unroll
    for (int i = 0; i < 4; i++)
        T[ty + 8 * i][tx] = W[(size_t)(k0 + ty + 8 * i) * D_ + n0 + tx];
    __syncthreads();
    #pragma unroll
    for (int i = 0; i < 4; i++) {
        int n = n0 + ty + 8 * i, k = k0 + tx;
        float v = T[tx][ty + 8 * i];
        __nv_bfloat16 hi = __float2bfloat16(v);
        size_t o = (size_t)(z * D_ + n) * D_ + k;
        g_wt_hi[o] = hi;
        g_wt_lo[o] = __float2bfloat16(v - __bfloat162float(hi));
    }
}

__global__ __launch_bounds__(256) void bias_prep_kernel(const float* __restrict__ bq,
                                                        const float* __restrict__ bk,
                                                        const float* __restrict__ bv) {
    int i = blockIdx.x * 256 + threadIdx.x;
    g_bias[i] = (i < D_) ? bq[i] : (i < 2 * D_) ? bk[i - D_] : bv[i - 2 * D_];
}

// ---------------- HMMA split-bf16 GEMM, fused 3-pass ----------------
// Per k-chunk (BK=32): load Ahi/Alo/Bhi/Blo once, issue hi*hi + hi*lo + lo*hi.
// smem per stage: 4 tiles x [128][40] bf16 = 40960 B; 2 stages = 81920 B.
#define NCHUNK 32
#define TILE_B 10240u
#define STAGE_B 40960u

__global__ __launch_bounds__(256, 2)
void gemm_hmma_kernel(int src_mode, int b_row0,
                      const float* __restrict__ bias, float* __restrict__ outp,
                      int qkv_scatter)
{
    extern __shared__ char smg[];
    const uint32_t s0 = smem_u32(smg);

    const int tid = threadIdx.x;
    const int wid = tid >> 5;
    const int lane = tid & 31;
    const int m0 = blockIdx.y * 128;
    const int n0 = blockIdx.x * 128;
    const int wm = wid & 1;
    const int wn = wid >> 1;

    const __nv_bfloat16* a_hi = src_mode ? g_att_hi : g_x_hi;
    const __nv_bfloat16* a_lo = src_mode ? g_att_lo : g_x_lo;

    const int seg = tid & 3;
    const int hr  = tid >> 2;

    float acc[4][4][4];
    #pragma unroll
    for (int i = 0; i < 4; i++)
        #pragma unroll
        for (int j = 0; j < 4; j++)
            acc[i][j][0] = acc[i][j][1] = acc[i][j][2] = acc[i][j][3] = 0.f;

    auto issue_load = [&](int c, int st) {
        const int k0 = c * 32;
        const uint32_t sb = s0 + st * STAGE_B + (uint32_t)(hr * 80 + seg * 16);
        const size_t goA = (size_t)(m0 + hr) * D_ + k0 + seg * 8;
        const size_t goB = (size_t)(b_row0 + n0 + hr) * D_ + k0 + seg * 8;
        cp16(sb + 0 * TILE_B, a_hi + goA);
        cp16(sb + 1 * TILE_B, a_lo + goA);
        cp16(sb + 2 * TILE_B, g_wt_hi + goB);
        cp16(sb + 3 * TILE_B, g_wt_lo + goB);
        cp16(sb + 0 * TILE_B + 64 * 80, a_hi + goA + (size_t)64 * D_);
        cp16(sb + 1 * TILE_B + 64 * 80, a_lo + goA + (size_t)64 * D_);
        cp16(sb + 2 * TILE_B + 64 * 80, g_wt_hi + goB + (size_t)64 * D_);
        cp16(sb + 3 * TILE_B + 64 * 80, g_wt_lo + goB + (size_t)64 * D_);
        cp_commit();
    };

    issue_load(0, 0);

    for (int c = 0; c < NCHUNK; ++c) {
        const int st = c & 1;
        if (c + 1 < NCHUNK) {
            issue_load(c + 1, st ^ 1);
            cp_wait<1>();
        } else {
            cp_wait<0>();
        }
        __syncthreads();

        const uint32_t aHB = s0 + st * STAGE_B;
        const uint32_t aLB = aHB + TILE_B;
        const uint32_t bHB = aHB + 2 * TILE_B;
        const uint32_t bLB = aHB + 3 * TILE_B;

        #pragma unroll
        for (int kk = 0; kk < 2; ++kk) {
            const uint32_t a_off = (uint32_t)((wm * 64 + (lane & 15)) * 80 +
                                              (kk * 2 + (lane >> 4)) * 16);
            const int bg   = lane >> 3;
            const uint32_t b_off0 = (uint32_t)((wn * 32 + ((bg & 2) ? 8 : 0) + (lane & 7)) * 80 +
                                               (kk * 2 + (bg & 1)) * 16);

            uint32_t afh[4][4], bfh[4][2];
            #pragma unroll
            for (int mt = 0; mt < 4; ++mt)
                ldsm4(afh[mt][0], afh[mt][1], afh[mt][2], afh[mt][3],
                      aHB + a_off + (uint32_t)mt * 16 * 80);
            #pragma unroll
            for (int j = 0; j < 2; ++j) {
                uint32_t r0, r1, r2, r3;
                ldsm4(r0, r1, r2, r3, bHB + b_off0 + (uint32_t)j * 16 * 80);
                bfh[j * 2 + 0][0] = r0; bfh[j * 2 + 0][1] = r1;
                bfh[j * 2 + 1][0] = r2; bfh[j * 2 + 1][1] = r3;
            }
            // pass 1: hi * hi
            #pragma unroll
            for (int mt = 0; mt < 4; ++mt)
                #pragma unroll
                for (int nt = 0; nt < 4; ++nt)
                    mma16816(acc[mt][nt], afh[mt], bfh[nt]);
            // pass 2: hi * lo  (reuse afh)
            {
                uint32_t bfl[4][2];
                #pragma unroll
                for (int j = 0; j < 2; ++j) {
                    uint32_t r0, r1, r2, r3;
                    ldsm4(r0, r1, r2, r3, bLB + b_off0 + (uint32_t)j * 16 * 80);
                    bfl[j * 2 + 0][0] = r0; bfl[j * 2 + 0][1] = r1;
                    bfl[j * 2 + 1][0] = r2; bfl[j * 2 + 1][1] = r3;
                }
                #pragma unroll
                for (int mt = 0; mt < 4; ++mt)
                    #pragma unroll
                    for (int nt = 0; nt < 4; ++nt)
                        mma16816(acc[mt][nt], afh[mt], bfl[nt]);
            }
            // pass 3: lo * hi  (reuse bfh)
            {
                uint32_t afl[4][4];
                #pragma unroll
                for (int mt = 0; mt < 4; ++mt)
                    ldsm4(afl[mt][0], afl[mt][1], afl[mt][2], afl[mt][3],
                          aLB + a_off + (uint32_t)mt * 16 * 80);
                #pragma unroll
                for (int mt = 0; mt < 4; ++mt)
                    #pragma unroll
                    for (int nt = 0; nt < 4; ++nt)
                        mma16816(acc[mt][nt], afl[mt], bfh[nt]);
            }
        }
        __syncthreads();
    }

    // ---- epilogue ----
    #pragma unroll
    for (int nt = 0; nt < 4; ++nt) {
        int ng = n0 + wn * 32 + nt * 8 + (lane & 3) * 2;
        float bx = bias[ng], by = bias[ng + 1];
        if (qkv_scatter) {
            int sel = ng >> 10;
            int nl  = ng & (D_ - 1);
            int hh  = nl >> 6;
            int dd  = nl & 63;
            float scale = (sel == 0) ? 0.125f * 1.44269504089f : 1.0f;  // fold softmax scale*log2e into Q
            __nv_bfloat16* dh = (sel == 0) ? g_qhi : (sel == 1) ? g_khi : g_vhi;
            __nv_bfloat16* dl = (sel == 0) ? g_qlo : (sel == 1) ? g_klo : g_vlo;
            #pragma unroll
            for (int mt = 0; mt < 4; ++mt) {
                #pragma unroll
                for (int h2 = 0; h2 < 2; ++h2) {
                    int row = m0 + wm * 64 + mt * 16 + (lane >> 2) + h2 * 8;
                    int bb = row >> 11, ss = row & (S_ - 1);
                    float vx = (acc[mt][nt][h2 * 2 + 0] + bx) * scale;
                    float vy = (acc[mt][nt][h2 * 2 + 1] + by) * scale;
                    size_t idx = (((size_t)bb * H_ + hh) * S_ + ss) * HD_ + dd;
                    *reinterpret_cast<uint32_t*>(dh + idx) = pack_hi(vx, vy);
                    *reinterpret_cast<uint32_t*>(dl + idx) = pack_lo_res(vx, vy);
                }
            }
        } else {
            #pragma unroll
            for (int mt = 0; mt < 4; ++mt) {
                #pragma unroll
                for (int h2 = 0; h2 < 2; ++h2) {
                    int row = m0 + wm * 64 + mt * 16 + (lane >> 2) + h2 * 8;
                    float2 v;
                    v.x = acc[mt][nt][h2 * 2 + 0] + bx;
                    v.y = acc[mt][nt][h2 * 2 + 1] + by;
                    *reinterpret_cast<float2*>(outp + (size_t)row * D_ + ng) = v;
                }
            }
        }
    }
}

// ---------------------------------------------------------------------------
// HMMA flash attention, fused-pass version. Layout identical to R11.
// Scores: per kk load Qhi,Qlo,Khi,Klo frags once -> 3 MMA combos.
// PV: per kk load Vhi,Vlo frags once -> Phi*Vhi + Phi*Vlo + Plo*Vhi.
// Softmax in base-2 domain (scale*log2e folded into Q).
// ---------------------------------------------------------------------------
#define ATT_SMEM 110592

__global__ __launch_bounds__(256, 2)
void attn_hmma_kernel()
{
    extern __shared__ char smc[];
    const uint32_t sb = smem_u32(smc);
    const int tid  = threadIdx.x;
    const int lane = tid & 31;
    const int wid  = tid >> 5;
    const int q0   = wid * 16;
    const int qt = blockIdx.x, h = blockIdx.y, b = blockIdx.z;

    const __nv_bfloat16* gqh = g_qhi + (((size_t)b * H_ + h) * S_ + qt * 128) * HD_;
    const __nv_bfloat16* gql = g_qlo + (((size_t)b * H_ + h) * S_ + qt * 128) * HD_;
    const __nv_bfloat16* gkh = g_khi + ((size_t)b * H_ + h) * S_ * HD_;
    const __nv_bfloat16* gkl = g_klo + ((size_t)b * H_ + h) * S_ * HD_;
    const __nv_bfloat16* gvh = g_vhi + ((size_t)b * H_ + h) * S_ * HD_;
    const __nv_bfloat16* gvl = g_vlo + ((size_t)b * H_ + h) * S_ * HD_;

    // Q tiles -> smem
    {
        int r  = tid >> 1;
        int s4 = (tid & 1) * 4;
        const __nv_bfloat16* sh = gqh + (size_t)r * HD_ + s4 * 8;
        const __nv_bfloat16* sl = gql + (size_t)r * HD_ + s4 * 8;
        uint32_t dh = sb + r * 144 + s4 * 16;
        uint32_t dl = sb + 18432 + r * 144 + s4 * 16;
        #pragma unroll
        for (int i = 0; i < 4; i++) {
            cp16(dh + i * 16, sh + i * 8);
            cp16(dl + i * 16, sl + i * 8);
        }
        cp_commit();
    }

    auto issue_kv = [&](int c, int st) {
        int r  = tid >> 2;
        int sg = (tid & 3) * 2;
        size_t go = (size_t)(c * 64 + r) * HD_ + sg * 8;
        uint32_t sd = sb + 36864 + st * 36864 + r * 144 + sg * 16;
        cp16(sd,              gkh + go); cp16(sd + 16,              gkh + go + 8);
        cp16(sd + 9216,       gkl + go); cp16(sd + 9216 + 16,       gkl + go + 8);
        cp16(sd + 18432,      gvh + go); cp16(sd + 18432 + 16,      gvh + go + 8);
        cp16(sd + 27648,      gvl + go); cp16(sd + 27648 + 16,      gvl + go + 8);
        cp_commit();
    };

    issue_kv(0, 0);

    float o[8][4];
    #pragma unroll
    for (int n = 0; n < 8; n++)
        o[n][0] = o[n][1] = o[n][2] = o[n][3] = 0.f;
    float mA = -1e30f, mB = -1e30f, lA = 0.f, lB = 0.f;

    const uint32_t qhb = sb, qlb = sb + 18432;
    const uint32_t a_row_off = (uint32_t)(q0 + (lane & 15)) * 144 + (lane >> 4) * 16;
    const uint32_t k_row_off = (uint32_t)(lane & 15) * 144 + (lane >> 4) * 16;

    for (int c = 0; c < S_ / 64; ++c) {
        const int st = c & 1;
        if (c + 1 < S_ / 64) {
            issue_kv(c + 1, st ^ 1);
            cp_wait<1>();
        } else {
            cp_wait<0>();
        }
        __syncthreads();

        const uint32_t kbh = sb + 36864 + st * 36864;
        const uint32_t kbl = kbh + 9216;
        const uint32_t vbh = kbh + 18432;
        const uint32_t vbl = kbh + 27648;

        float s[8][4];
        #pragma unroll
        for (int n = 0; n < 8; n++)
            s[n][0] = s[n][1] = s[n][2] = s[n][3] = 0.f;

        // ---- scores, fused 3 passes ----
        #pragma unroll
        for (int kk = 0; kk < 4; kk++) {
            uint32_t ah[4], al[4];
            ldsm4(ah[0], ah[1], ah[2], ah[3], qhb + a_row_off + kk * 32);
            ldsm4(al[0], al[1], al[2], al[3], qlb + a_row_off + kk * 32);
            #pragma unroll
            for (int g = 0; g < 4; g++) {
                uint32_t r0, r1, r2, r3;
                ldsm4(r0, r1, r2, r3, kbh + k_row_off + (uint32_t)g * 16 * 144 + kk * 32);
                uint32_t bh0[2] = {r0, r2}, bh1[2] = {r1, r3};
                mma16816(s[2 * g],     ah, bh0);
                mma16816(s[2 * g + 1], ah, bh1);
                mma16816(s[2 * g],     al, bh0);
                mma16816(s[2 * g + 1], al, bh1);
                ldsm4(r0, r1, r2, r3, kbl + k_row_off + (uint32_t)g * 16 * 144 + kk * 32);
                uint32_t bl0[2] = {r0, r2}, bl1[2] = {r1, r3};
                mma16816(s[2 * g],     ah, bl0);
                mma16816(s[2 * g + 1], ah, bl1);
            }
        }

        // ---- online softmax (base-2 domain) ----
        float mxA = -1e30f, mxB = -1e30f;
        #pragma unroll
        for (int n = 0; n < 8; n++) {
            mxA = fmaxf(mxA, fmaxf(s[n][0], s[n][1]));
            mxB = fmaxf(mxB, fmaxf(s[n][2], s[n][3]));
        }
        mxA = fmaxf(mxA, __shfl_xor_sync(0xffffffffu, mxA, 1));
        mxA = fmaxf(mxA, __shfl_xor_sync(0xffffffffu, mxA, 2));
        mxB = fmaxf(mxB, __shfl_xor_sync(0xffffffffu, mxB, 1));
        mxB = fmaxf(mxB, __shfl_xor_sync(0xffffffffu, mxB, 2));
        float mnA = fmaxf(mA, mxA), mnB = fmaxf(mB, mxB);
        float cA = exp2f(mA - mnA), cB = exp2f(mB - mnB);
        float psA = 0.f, psB = 0.f;
        #pragma unroll
        for (int n = 0; n < 8; n++) {
            s[n][0] = exp2f(s[n][0] - mnA); psA += s[n][0];
            s[n][1] = exp2f(s[n][1] - mnA); psA += s[n][1];
            s[n][2] = exp2f(s[n][2] - mnB); psB += s[n][2];
            s[n][3] = exp2f(s[n][3] - mnB); psB += s[n][3];
        }
        psA += __shfl_xor_sync(0xffffffffu, psA, 1);
        psA += __shfl_xor_sync(0xffffffffu, psA, 2);
        psB += __shfl_xor_sync(0xffffffffu, psB, 1);
        psB += __shfl_xor_sync(0xffffffffu, psB, 2);
        lA = lA * cA + psA; lB = lB * cB + psB;
        mA = mnA; mB = mnB;
        #pragma unroll
        for (int n = 0; n < 8; n++) {
            o[n][0] *= cA; o[n][1] *= cA; o[n][2] *= cB; o[n][3] *= cB;
        }

        // ---- PV, fused 3 passes ----
        #pragma unroll
        for (int kk = 0; kk < 4; kk++) {
            uint32_t phi[4], pl[4];
            phi[0] = pack_hi(s[2 * kk][0],     s[2 * kk][1]);
            phi[1] = pack_hi(s[2 * kk][2],     s[2 * kk][3]);
            phi[2] = pack_hi(s[2 * kk + 1][0], s[2 * kk + 1][1]);
            phi[3] = pack_hi(s[2 * kk + 1][2], s[2 * kk + 1][3]);
            pl[0] = pack_lo_res(s[2 * kk][0],     s[2 * kk][1]);
            pl[1] = pack_lo_res(s[2 * kk][2],     s[2 * kk][3]);
            pl[2] = pack_lo_res(s[2 * kk + 1][0], s[2 * kk + 1][1]);
            pl[3] = pack_lo_res(s[2 * kk + 1][2], s[2 * kk + 1][3]);
            #pragma unroll
            for (int g = 0; g < 4; g++) {
                uint32_t r0, r1, r2, r3;
                ldsm4t(r0, r1, r2, r3,
                       vbh + k_row_off + (uint32_t)kk * 16 * 144 + g * 32);
                uint32_t bh0[2] = {r0, r1}, bh1[2] = {r2, r3};
                mma16816(o[2 * g],     phi, bh0);
                mma16816(o[2 * g + 1], phi, bh1);
                mma16816(o[2 * g],     pl,  bh0);
                mma16816(o[2 * g + 1], pl,  bh1);
                ldsm4t(r0, r1, r2, r3,
                       vbl + k_row_off + (uint32_t)kk * 16 * 144 + g * 32);
                uint32_t bl0[2] = {r0, r1}, bl1[2] = {r2, r3};
                mma16816(o[2 * g],     phi, bl0);
                mma16816(o[2 * g + 1], phi, bl1);
            }
        }
        __syncthreads();
    }

    // ---- epilogue: normalize, split bf16 hi/lo into g_att ----
    float invA = 1.f / lA, invB = 1.f / lB;
    int rowA = qt * 128 + q0 + (lane >> 2);
    int rowB = rowA + 8;
    size_t baseA = ((size_t)b * S_ + rowA) * D_ + h * HD_ + (lane & 3) * 2;
    size_t baseB = ((size_t)b * S_ + rowB) * D_ + h * HD_ + (lane & 3) * 2;
    #pragma unroll
    for (int n = 0; n < 8; n++) {
        float ax = o[n][0] * invA, ay = o[n][1] * invA;
        float bx = o[n][2] * invB, by = o[n][3] * invB;
        *reinterpret_cast<uint32_t*>(g_att_hi + baseA + n * 8) = pack_hi(ax, ay);
        *reinterpret_cast<uint32_t*>(g_att_lo + baseA + n * 8) = pack_lo_res(ax, ay);
        *reinterpret_cast<uint32_t*>(g_att_hi + baseB + n * 8) = pack_hi(bx, by);
        *reinterpret_cast<uint32_t*>(g_att_lo + baseB + n * 8) = pack_lo_res(bx, by);
    }
}

// ---------------------------------------------------------------------------
extern "C" void kernel_launch(void* const* d_in, const int* in_sizes, int n_in,
                              void* d_out, int out_size)
{
    const float* x  = (const float*)d_in[0];
    const float* Wq = (const float*)d_in[1];
    const float* bq = (const float*)d_in[2];
    const float* Wk = (const float*)d_in[3];
    const float* bk = (const float*)d_in[4];
    const float* Wv = (const float*)d_in[5];
    const float* bv = (const float*)d_in[6];
    const float* Wo = (const float*)d_in[7];
    const float* bo = (const float*)d_in[8];
    float* out = (float*)d_out;

    cudaFuncSetAttribute(attn_hmma_kernel, cudaFuncAttributeMaxDynamicSharedMemorySize, ATT_SMEM);
    cudaFuncSetAttribute(gemm_hmma_kernel, cudaFuncAttributeMaxDynamicSharedMemorySize,
                         (int)(2 * STAGE_B));

    // prep
    x_prep_kernel<<<M_ * D_ / 4 / 256, 256>>>(x);
    dim3 wgrid(D_ / 32, D_ / 32, 4);
    w_prep_kernel<<<wgrid, 256>>>(Wq, Wk, Wv, Wo);
    bias_prep_kernel<<<3 * D_ / 256, 256>>>(bq, bk, bv);

    // QKV projection: C[4096 x 3072] -> split bf16 q/k/v (head-major)
    dim3 qkv_grid(3 * D_ / 128, M_ / 128);
    gemm_hmma_kernel<<<qkv_grid, 256, 2 * STAGE_B>>>(0, 0, g_bias, nullptr, 1);

    // attention
    dim3 attn_grid(S_ / 128, H_, B_);
    attn_hmma_kernel<<<attn_grid, 256, ATT_SMEM>>>();

    // output projection: C[4096 x 1024]
    dim3 out_grid(D_ / 128, M_ / 128);
    gemm_hmma_kernel<<<out_grid, 256, 2 * STAGE_B>>>(1, 3 * D_, bo, out, 0);
}